// round 1
// baseline (speedup 1.0000x reference)
#include <cuda_runtime.h>
#include <cstdint>

// Problem constants (fixed shapes)
#define NROWS 32768        // B*T
#define KCODES 8192
#define DDIM 256
#define GAMMA_F 0.99f
#define ONE_MG 0.01f       // float32(1.0 - 0.99) rounds identically
#define EPS_F 1e-5f
#define KEPS_F 0.08192f    // K * EPS

// Output layout (flattened tuple, float32)
#define OFF_ZQ     ((size_t)0)
#define OFF_COMMIT ((size_t)8388608)
#define OFF_IDX    ((size_t)8388609)
#define OFF_EW     ((size_t)8421377)
#define OFF_MT     ((size_t)10518529)
#define OFF_NT     ((size_t)12615681)

// Scratch (device globals — no allocation allowed)
__device__ float  g_wnorm[KCODES];
__device__ int    g_idx[NROWS];
__device__ double g_commit;
__device__ float  g_n;

// ---- packed f32x2 helpers ----
#define PACK_DUP(out64, f32val) do {                                   \
    unsigned int _u = __float_as_uint(f32val);                         \
    asm("mov.b64 %0, {%1, %1};" : "=l"(out64) : "r"(_u));              \
} while (0)

#define FMA2(acc, a, b)                                                \
    asm("fma.rn.f32x2 %0, %1, %2, %0;" : "+l"(acc) : "l"(a), "l"(b))

#define UNPACK2(lo, hi, v64) do {                                      \
    unsigned int _l, _h;                                               \
    asm("mov.b64 {%0, %1}, %2;" : "=r"(_l), "=r"(_h) : "l"(v64));      \
    lo = __uint_as_float(_l); hi = __uint_as_float(_h);                \
} while (0)

// ---------------------------------------------------------------------------
// k_init: seed EMA outputs (gamma * old), zero commit accumulator
// ---------------------------------------------------------------------------
__global__ void k_init(const float* __restrict__ mt, const float* __restrict__ Nt,
                       float* __restrict__ out)
{
    int i = blockIdx.x * blockDim.x + threadIdx.x;
    if (i == 0) g_commit = 0.0;
    if (i < KCODES) out[OFF_NT + i] = GAMMA_F * Nt[i];
    const int total = KCODES * DDIM;
    const int stride = gridDim.x * blockDim.x;
    for (int j = i; j < total; j += stride)
        out[OFF_MT + j] = GAMMA_F * mt[j];
}

// ---------------------------------------------------------------------------
// k_wnorm: per-code squared norms (one warp per code)
// ---------------------------------------------------------------------------
__global__ void k_wnorm(const float* __restrict__ W)
{
    int warp = (blockIdx.x * blockDim.x + threadIdx.x) >> 5;
    int lane = threadIdx.x & 31;
    if (warp >= KCODES) return;
    const float* w = W + (size_t)warp * DDIM;
    float s = 0.f;
#pragma unroll
    for (int j = 0; j < 8; j++) { float v = w[lane + 32 * j]; s = fmaf(v, v, s); }
#pragma unroll
    for (int off = 16; off >= 1; off >>= 1)
        s += __shfl_xor_sync(0xffffffffu, s, off);
    if (lane == 0) g_wnorm[warp] = s;
}

// ---------------------------------------------------------------------------
// k_argmin: the 32768 x 8192 x 256 distance GEMM + running argmin.
// CTA tile: 128 rows x 128 codes, K-chunk 32. 256 threads = 16(tx codes) x 16(ty rows),
// each thread: 8 rows x 8 codes via packed fma.rn.f32x2 (codes paired).
// ---------------------------------------------------------------------------
__global__ __launch_bounds__(256, 2)
void k_argmin(const float* __restrict__ ze, const float* __restrict__ W,
              float* __restrict__ out_idx)
{
    __shared__ __align__(16) float sZ[32][132];  // [d][row], padded
    __shared__ __align__(16) float sW[32][132];  // [d][code], padded

    const int t  = threadIdx.x;
    const int tx = t & 15;
    const int ty = t >> 4;
    const int rowBase = blockIdx.x * 128;

    float minv[8];
    int   mini[8];
#pragma unroll
    for (int i = 0; i < 8; i++) { minv[i] = 3.4e38f; mini[i] = 0; }

    for (int nc = 0; nc < KCODES / 128; ++nc) {
        unsigned long long acc[8][4];
#pragma unroll
        for (int i = 0; i < 8; i++)
#pragma unroll
            for (int j = 0; j < 4; j++) acc[i][j] = 0ull;

        const int cBase = nc * 128;
        for (int dk = 0; dk < 8; ++dk) {
            __syncthreads();
            // stage 128x32 chunks of Z and W (transposed into [d][row])
#pragma unroll
            for (int i = 0; i < 4; i++) {
                int e  = t * 4 + i;        // 0..1023 float4 slots
                int r  = e >> 3;           // 0..127
                int d4 = e & 7;            // 0..7 float4 within 32 floats
                float4 zv = *(const float4*)&ze[(size_t)(rowBase + r) * DDIM + dk * 32 + d4 * 4];
                float4 wv = *(const float4*)&W [(size_t)(cBase  + r) * DDIM + dk * 32 + d4 * 4];
                sZ[d4 * 4 + 0][r] = zv.x; sZ[d4 * 4 + 1][r] = zv.y;
                sZ[d4 * 4 + 2][r] = zv.z; sZ[d4 * 4 + 3][r] = zv.w;
                sW[d4 * 4 + 0][r] = wv.x; sW[d4 * 4 + 1][r] = wv.y;
                sW[d4 * 4 + 2][r] = wv.z; sW[d4 * 4 + 3][r] = wv.w;
            }
            __syncthreads();

#pragma unroll
            for (int kk = 0; kk < 32; ++kk) {
                float4 a0 = *(const float4*)&sZ[kk][ty * 8];
                float4 a1 = *(const float4*)&sZ[kk][ty * 8 + 4];
                const ulonglong2* bp = (const ulonglong2*)&sW[kk][tx * 8];
                ulonglong2 b01 = bp[0];
                ulonglong2 b23 = bp[1];
                float av[8] = {a0.x, a0.y, a0.z, a0.w, a1.x, a1.y, a1.z, a1.w};
#pragma unroll
                for (int i = 0; i < 8; i++) {
                    unsigned long long ap;
                    PACK_DUP(ap, av[i]);
                    FMA2(acc[i][0], ap, b01.x);
                    FMA2(acc[i][1], ap, b01.y);
                    FMA2(acc[i][2], ap, b23.x);
                    FMA2(acc[i][3], ap, b23.y);
                }
            }
        }

        // epilogue: dist = ||w||^2 - 2 z.w  (||z||^2 is row-constant -> argmin invariant)
        const int cT = cBase + tx * 8;
#pragma unroll
        for (int i = 0; i < 8; i++) {
#pragma unroll
            for (int jp = 0; jp < 4; jp++) {
                float lo, hi;
                UNPACK2(lo, hi, acc[i][jp]);
                int c0 = cT + 2 * jp;
                float d0 = g_wnorm[c0]     - 2.0f * lo;
                float d1 = g_wnorm[c0 + 1] - 2.0f * hi;
                if (d0 < minv[i]) { minv[i] = d0; mini[i] = c0; }
                if (d1 < minv[i]) { minv[i] = d1; mini[i] = c0 + 1; }
            }
        }
    }

    // reduce argmin across the 16 tx lanes (lowest value; tie -> lowest index)
#pragma unroll
    for (int i = 0; i < 8; i++) {
        float v = minv[i]; int ix = mini[i];
#pragma unroll
        for (int off = 8; off >= 1; off >>= 1) {
            float ov = __shfl_xor_sync(0xffffffffu, v, off);
            int   oi = __shfl_xor_sync(0xffffffffu, ix, off);
            if (ov < v || (ov == v && oi < ix)) { v = ov; ix = oi; }
        }
        if (tx == 0) {
            int row = rowBase + ty * 8 + i;
            g_idx[row] = ix;
            out_idx[row] = (float)ix;
        }
    }
}

// ---------------------------------------------------------------------------
// k_gather: zq_st output, commit partial sums, EMA scatter (atomics)
// One warp per row.
// ---------------------------------------------------------------------------
__global__ void k_gather(const float* __restrict__ ze, const float* __restrict__ W,
                         float* __restrict__ out)
{
    int wInB = threadIdx.x >> 5;
    int lane = threadIdx.x & 31;
    int row  = blockIdx.x * 8 + wInB;
    int idx  = g_idx[row];
    const float* z = ze + (size_t)row * DDIM;
    const float* w = W  + (size_t)idx * DDIM;
    float c = 0.f;
#pragma unroll
    for (int j = 0; j < 8; j++) {
        int d = lane + 32 * j;
        float wv = w[d], zv = z[d];
        float df = wv - zv;
        out[OFF_ZQ + (size_t)row * DDIM + d] = zv + df;  // replicate straight-through rounding
        c = fmaf(df, df, c);
        atomicAdd(&out[OFF_MT + (size_t)idx * DDIM + d], ONE_MG * zv);
    }
#pragma unroll
    for (int off = 16; off >= 1; off >>= 1)
        c += __shfl_xor_sync(0xffffffffu, c, off);
    if (lane == 0) {
        atomicAdd(&g_commit, (double)c);
        atomicAdd(&out[OFF_NT + idx], ONE_MG);
    }
}

// ---------------------------------------------------------------------------
// k_reduce: n = sum(Nt_new); finalize commit
// ---------------------------------------------------------------------------
__global__ void k_reduce(float* __restrict__ out)
{
    __shared__ float sb[256];
    float s = 0.f;
    for (int i = threadIdx.x; i < KCODES; i += 256) s += out[OFF_NT + i];
    sb[threadIdx.x] = s;
    __syncthreads();
    for (int off = 128; off >= 1; off >>= 1) {
        if (threadIdx.x < off) sb[threadIdx.x] += sb[threadIdx.x + off];
        __syncthreads();
    }
    if (threadIdx.x == 0) {
        g_n = sb[0];
        out[OFF_COMMIT] = (float)(g_commit / (double)(NROWS * DDIM));
    }
}

// ---------------------------------------------------------------------------
// k_final: embedW_new = mt_new * (n + K*eps) / ((Nt_new + eps) * n)
// ---------------------------------------------------------------------------
__global__ void k_final(float* __restrict__ out)
{
    int i = blockIdx.x * blockDim.x + threadIdx.x;
    if (i >= KCODES * DDIM) return;
    int k = i >> 8;
    float n  = g_n;
    float nt = out[OFF_NT + k];
    float scale = (n + KEPS_F) / ((nt + EPS_F) * n);
    out[OFF_EW + i] = out[OFF_MT + i] * scale;
}

// ---------------------------------------------------------------------------
extern "C" void kernel_launch(void* const* d_in, const int* in_sizes, int n_in,
                              void* d_out, int out_size)
{
    const float* ze = (const float*)d_in[0];
    const float* W  = (const float*)d_in[1];
    const float* mt = (const float*)d_in[2];
    const float* Nt = (const float*)d_in[3];
    float* out = (float*)d_out;

    k_init  <<<2048, 256>>>(mt, Nt, out);
    k_wnorm <<<(KCODES * 32) / 256, 256>>>(W);
    k_argmin<<<NROWS / 128, 256>>>(ze, W, out + OFF_IDX);
    k_gather<<<NROWS / 8, 256>>>(ze, W, out);
    k_reduce<<<1, 256>>>(out);
    k_final <<<(KCODES * DDIM) / 256, 256>>>(out);
}